// round 2
// baseline (speedup 1.0000x reference)
#include <cuda_runtime.h>
#include <math.h>

#define NS 1024
#define NR 4096
#define TPB 256

// ---------------- scratch (static device globals; no allocation) ----------------
__device__ __align__(16) float g_true_c[NR * 3];   // centered true coords
__device__ __align__(16) float g_w[NR];            // mask as float weights
__device__ float g_stats[8];                       // [0..2]=tmean, [3]=Lt, [4]=1/Lt, [5]=1/d0^2
__device__ float g_S[NS * 12];                     // per sample: S00..S22 (row-major), psum x/y/z
__device__ float g_RT[NS * 12];                    // per sample: R (row-major 9), c = R*pmean (3)

__device__ __forceinline__ float warpsum(float v) {
#pragma unroll
    for (int o = 16; o; o >>= 1) v += __shfl_down_sync(0xffffffffu, v, o);
    return v;
}

// ---------------- kernel A: true-structure statistics ----------------
__global__ void k_true(const float* __restrict__ truec, const int* __restrict__ mask) {
    int tid = threadIdx.x;
    float ws = 0.f, wt0 = 0.f, wt1 = 0.f, wt2 = 0.f;
    for (int l = tid; l < NR; l += TPB) {
        float w = (mask[l] != 0) ? 1.0f : 0.0f;
        g_w[l] = w;
        float t0 = truec[l * 3 + 0];
        float t1 = truec[l * 3 + 1];
        float t2 = truec[l * 3 + 2];
        ws += w; wt0 += w * t0; wt1 += w * t1; wt2 += w * t2;
    }
    __shared__ float sm[4][8];
    __shared__ float s_tm[3];
    int lane = tid & 31, wid = tid >> 5;
    ws = warpsum(ws); wt0 = warpsum(wt0); wt1 = warpsum(wt1); wt2 = warpsum(wt2);
    if (lane == 0) { sm[0][wid] = ws; sm[1][wid] = wt0; sm[2][wid] = wt1; sm[3][wid] = wt2; }
    __syncthreads();
    if (tid == 0) {
        float Lt = 0.f, a = 0.f, b = 0.f, c = 0.f;
        for (int i = 0; i < 8; i++) { Lt += sm[0][i]; a += sm[1][i]; b += sm[2][i]; c += sm[3][i]; }
        float inv = 1.0f / Lt;
        float m0 = a * inv, m1 = b * inv, m2 = c * inv;
        float d0 = (Lt <= 15.0f) ? 0.5f : (1.24f * cbrtf(Lt - 15.0f) - 1.8f);
        d0 = fmaxf(d0, 0.5f);
        g_stats[0] = m0; g_stats[1] = m1; g_stats[2] = m2;
        g_stats[3] = Lt; g_stats[4] = inv; g_stats[5] = 1.0f / (d0 * d0);
        s_tm[0] = m0; s_tm[1] = m1; s_tm[2] = m2;
    }
    __syncthreads();
    float m0 = s_tm[0], m1 = s_tm[1], m2 = s_tm[2];
    for (int l = tid; l < NR; l += TPB) {
        g_true_c[l * 3 + 0] = truec[l * 3 + 0] - m0;
        g_true_c[l * 3 + 1] = truec[l * 3 + 1] - m1;
        g_true_c[l * 3 + 2] = truec[l * 3 + 2] - m2;
    }
}

// ---------------- kernel B: per-sample covariance + pred sum ----------------
// H_ij = sum_l w_l * pred_raw_i * true_c_j   (valid because sum_l w_l * true_c = 0)
#define ROW_ACC(w_, px, py, pz, tx, ty, tz) do { \
    float wx = (w_) * (px), wy = (w_) * (py), wz = (w_) * (pz); \
    S00 = fmaf(wx, (tx), S00); S01 = fmaf(wx, (ty), S01); S02 = fmaf(wx, (tz), S02); \
    S10 = fmaf(wy, (tx), S10); S11 = fmaf(wy, (ty), S11); S12 = fmaf(wy, (tz), S12); \
    S20 = fmaf(wz, (tx), S20); S21 = fmaf(wz, (ty), S21); S22 = fmaf(wz, (tz), S22); \
    P0 += wx; P1 += wy; P2 += wz; } while (0)

__global__ void k_cov(const float* __restrict__ pred) {
    int s = blockIdx.x;
    int tid = threadIdx.x;
    const float4* __restrict__ p4 = reinterpret_cast<const float4*>(pred + (size_t)s * NR * 3);
    const float4* __restrict__ t4 = reinterpret_cast<const float4*>(g_true_c);
    const float4* __restrict__ w4 = reinterpret_cast<const float4*>(g_w);

    float S00 = 0, S01 = 0, S02 = 0, S10 = 0, S11 = 0, S12 = 0, S20 = 0, S21 = 0, S22 = 0;
    float P0 = 0, P1 = 0, P2 = 0;

#pragma unroll 4
    for (int g = tid; g < NR / 4; g += TPB) {
        float4 a = p4[3 * g + 0];
        float4 b = p4[3 * g + 1];
        float4 c = p4[3 * g + 2];
        float4 ta = t4[3 * g + 0];
        float4 tb = t4[3 * g + 1];
        float4 tc = t4[3 * g + 2];
        float4 wv = w4[g];
        ROW_ACC(wv.x, a.x, a.y, a.z, ta.x, ta.y, ta.z);
        ROW_ACC(wv.y, a.w, b.x, b.y, ta.w, tb.x, tb.y);
        ROW_ACC(wv.z, b.z, b.w, c.x, tb.z, tb.w, tc.x);
        ROW_ACC(wv.w, c.y, c.z, c.w, tc.y, tc.z, tc.w);
    }

    __shared__ float red[12][8];
    int lane = tid & 31, wid = tid >> 5;
    float vals[12] = {S00, S01, S02, S10, S11, S12, S20, S21, S22, P0, P1, P2};
#pragma unroll
    for (int k = 0; k < 12; k++) {
        float v = warpsum(vals[k]);
        if (lane == 0) red[k][wid] = v;
    }
    __syncthreads();
    if (tid < 12) {
        float v = 0.f;
#pragma unroll
        for (int i = 0; i < 8; i++) v += red[tid][i];
        g_S[s * 12 + tid] = v;
    }
}

// ---------------- kernel C: Horn quaternion Kabsch (per-sample rotation) ----------------
__global__ void k_rot() {
    int s = blockIdx.x * blockDim.x + threadIdx.x;
    if (s >= NS) return;

    float Sf[12];
#pragma unroll
    for (int i = 0; i < 12; i++) Sf[i] = g_S[s * 12 + i];
    float Sxx = Sf[0], Sxy = Sf[1], Sxz = Sf[2];
    float Syx = Sf[3], Syy = Sf[4], Syz = Sf[5];
    float Szx = Sf[6], Szy = Sf[7], Szz = Sf[8];

    float A[4][4];
    A[0][0] = Sxx + Syy + Szz; A[0][1] = Syz - Szy;        A[0][2] = Szx - Sxz;        A[0][3] = Sxy - Syx;
    A[1][1] = Sxx - Syy - Szz; A[1][2] = Sxy + Syx;        A[1][3] = Szx + Sxz;
    A[2][2] = -Sxx + Syy - Szz; A[2][3] = Syz + Szy;
    A[3][3] = -Sxx - Syy + Szz;
    A[1][0] = A[0][1]; A[2][0] = A[0][2]; A[3][0] = A[0][3];
    A[2][1] = A[1][2]; A[3][1] = A[1][3]; A[3][2] = A[2][3];

    float V[4][4] = {{1, 0, 0, 0}, {0, 1, 0, 0}, {0, 0, 1, 0}, {0, 0, 0, 1}};

    for (int sweep = 0; sweep < 12; sweep++) {
#pragma unroll
        for (int p = 0; p < 3; p++) {
#pragma unroll
            for (int q = p + 1; q < 4; q++) {
                float apq = A[p][q];
                float scale = fabsf(A[p][p]) + fabsf(A[q][q]);
                if (fabsf(apq) > 1e-12f * scale + 1e-30f) {
                    float theta = (A[q][q] - A[p][p]) / (2.0f * apq);
                    float t = 1.0f / (fabsf(theta) + sqrtf(theta * theta + 1.0f));
                    if (theta < 0.0f) t = -t;
                    float cth = 1.0f / sqrtf(t * t + 1.0f);
                    float sth = t * cth;
#pragma unroll
                    for (int r = 0; r < 4; r++) {
                        float arp = A[r][p], arq = A[r][q];
                        A[r][p] = arp * cth - arq * sth;
                        A[r][q] = arp * sth + arq * cth;
                    }
#pragma unroll
                    for (int r = 0; r < 4; r++) {
                        float apr = A[p][r], aqr = A[q][r];
                        A[p][r] = apr * cth - aqr * sth;
                        A[q][r] = apr * sth + aqr * cth;
                    }
#pragma unroll
                    for (int r = 0; r < 4; r++) {
                        float vrp = V[r][p], vrq = V[r][q];
                        V[r][p] = vrp * cth - vrq * sth;
                        V[r][q] = vrp * sth + vrq * cth;
                    }
                }
            }
        }
    }

    int k = 0;
    float best = A[0][0];
#pragma unroll
    for (int i = 1; i < 4; i++) if (A[i][i] > best) { best = A[i][i]; k = i; }
    float q0 = V[0][k], qx = V[1][k], qy = V[2][k], qz = V[3][k];

    float R[3][3];
    R[0][0] = q0 * q0 + qx * qx - qy * qy - qz * qz;
    R[0][1] = 2.0f * (qx * qy - q0 * qz);
    R[0][2] = 2.0f * (qx * qz + q0 * qy);
    R[1][0] = 2.0f * (qy * qx + q0 * qz);
    R[1][1] = q0 * q0 - qx * qx + qy * qy - qz * qz;
    R[1][2] = 2.0f * (qy * qz - q0 * qx);
    R[2][0] = 2.0f * (qz * qx - q0 * qy);
    R[2][1] = 2.0f * (qz * qy + q0 * qx);
    R[2][2] = q0 * q0 - qx * qx - qy * qy + qz * qz;

    // Orientation safeguard: objective = sum_l w * t . (R p) = sum_ij R_ij S_ji
    float Sm[3][3] = {{Sxx, Sxy, Sxz}, {Syx, Syy, Syz}, {Szx, Szy, Szz}};
    float obj = 0.f, objT = 0.f;
#pragma unroll
    for (int i = 0; i < 3; i++)
#pragma unroll
        for (int j = 0; j < 3; j++) {
            obj  += R[i][j] * Sm[j][i];
            objT += R[j][i] * Sm[j][i];
        }
    if (objT > obj) {
#pragma unroll
        for (int i = 0; i < 3; i++)
#pragma unroll
            for (int j = i + 1; j < 3; j++) {
                float tmp = R[i][j]; R[i][j] = R[j][i]; R[j][i] = tmp;
            }
    }

    float invLt = g_stats[4];
    float pm0 = Sf[9] * invLt, pm1 = Sf[10] * invLt, pm2 = Sf[11] * invLt;
    float c0 = R[0][0] * pm0 + R[0][1] * pm1 + R[0][2] * pm2;
    float c1 = R[1][0] * pm0 + R[1][1] * pm1 + R[1][2] * pm2;
    float c2 = R[2][0] * pm0 + R[2][1] * pm1 + R[2][2] * pm2;

    int base = s * 12;
    g_RT[base + 0] = R[0][0]; g_RT[base + 1] = R[0][1]; g_RT[base + 2] = R[0][2];
    g_RT[base + 3] = R[1][0]; g_RT[base + 4] = R[1][1]; g_RT[base + 5] = R[1][2];
    g_RT[base + 6] = R[2][0]; g_RT[base + 7] = R[2][1]; g_RT[base + 8] = R[2][2];
    g_RT[base + 9] = c0; g_RT[base + 10] = c1; g_RT[base + 11] = c2;
}

// ---------------- kernel D: TM-score evaluation ----------------
#define ROW_TM(w_, px, py, pz, tx, ty, tz) do { \
    float dx = fmaf(R00, (px), fmaf(R01, (py), fmaf(R02, (pz), -c0))) - (tx); \
    float dy = fmaf(R10, (px), fmaf(R11, (py), fmaf(R12, (pz), -c1))) - (ty); \
    float dz = fmaf(R20, (px), fmaf(R21, (py), fmaf(R22, (pz), -c2))) - (tz); \
    float dsq = fmaf(dx, dx, fmaf(dy, dy, dz * dz)); \
    acc += (w_) * __frcp_rn(fmaf(dsq, invd0, 1.0f)); } while (0)

__global__ void k_tm(const float* __restrict__ pred, float* __restrict__ out) {
    int s = blockIdx.x;
    int tid = threadIdx.x;
    __shared__ float P[14];
    if (tid < 12) P[tid] = g_RT[s * 12 + tid];
    if (tid == 12) P[12] = g_stats[5];
    if (tid == 13) P[13] = g_stats[4];
    __syncthreads();
    float R00 = P[0], R01 = P[1], R02 = P[2];
    float R10 = P[3], R11 = P[4], R12 = P[5];
    float R20 = P[6], R21 = P[7], R22 = P[8];
    float c0 = P[9], c1 = P[10], c2 = P[11];
    float invd0 = P[12], invLt = P[13];

    const float4* __restrict__ p4 = reinterpret_cast<const float4*>(pred + (size_t)s * NR * 3);
    const float4* __restrict__ t4 = reinterpret_cast<const float4*>(g_true_c);
    const float4* __restrict__ w4 = reinterpret_cast<const float4*>(g_w);

    float acc = 0.f;
#pragma unroll 4
    for (int g = tid; g < NR / 4; g += TPB) {
        float4 a = p4[3 * g + 0];
        float4 b = p4[3 * g + 1];
        float4 c = p4[3 * g + 2];
        float4 ta = t4[3 * g + 0];
        float4 tb = t4[3 * g + 1];
        float4 tc = t4[3 * g + 2];
        float4 wv = w4[g];
        ROW_TM(wv.x, a.x, a.y, a.z, ta.x, ta.y, ta.z);
        ROW_TM(wv.y, a.w, b.x, b.y, ta.w, tb.x, tb.y);
        ROW_TM(wv.z, b.z, b.w, c.x, tb.z, tb.w, tc.x);
        ROW_TM(wv.w, c.y, c.z, c.w, tc.y, tc.z, tc.w);
    }

    __shared__ float red[8];
    int lane = tid & 31, wid = tid >> 5;
    acc = warpsum(acc);
    if (lane == 0) red[wid] = acc;
    __syncthreads();
    if (tid == 0) {
        float v = 0.f;
#pragma unroll
        for (int i = 0; i < 8; i++) v += red[i];
        out[s] = v * invLt;
    }
}

// ---------------- launch ----------------
extern "C" void kernel_launch(void* const* d_in, const int* in_sizes, int n_in,
                              void* d_out, int out_size) {
    const float* pred = (const float*)d_in[0];
    const float* truec = (const float*)d_in[1];
    const int* mask = (const int*)d_in[2];
    float* out = (float*)d_out;

    k_true<<<1, TPB>>>(truec, mask);
    k_cov<<<NS, TPB>>>(pred);
    k_rot<<<8, 128>>>();
    k_tm<<<NS, TPB>>>(pred, out);
}